// round 1
// baseline (speedup 1.0000x reference)
#include <cuda_runtime.h>
#include <math.h>

// Problem constants
// b=8, c=192, h=w=128, heads=8, ch=24, hw=16384, 3c=576
#define HW 16384
#define C3 576
#define CC 192
#define NB 8

// Scratch (allocation-free rule: __device__ globals)
__device__ float g_qkv_pre[75497472];   // [8,576,16384]
__device__ float g_qkv_post[75497472];  // [8,576,16384]
__device__ float g_sumsq[8 * 384];      // q,k channel sum-of-squares
__device__ float g_Spart[64 * 8 * 576]; // split-K partials of q.k^T
__device__ float g_W2[8 * 192 * 192];   // folded proj x attn matrix per batch

// ---------------------------------------------------------------------------
// Zero-init small buffer
__global__ void zero_kernel(float* p, int n) {
    int i = blockIdx.x * blockDim.x + threadIdx.x;
    if (i < n) p[i] = 0.f;
}

// ---------------------------------------------------------------------------
// Tiled fp32 GEMM: O[b] = A[b] (MxK, row-major) * X[b] (KxN, row-major)
// BM=BN=64, BK=16, 256 threads, 4x4 per thread. M%64==0, N%64==0, K%16==0.
__global__ void gemm64x64(const float* __restrict__ A, long aBS,
                          const float* __restrict__ X, long xBS,
                          float* __restrict__ O, long oBS,
                          int M, int K, int N)
{
    __shared__ float As[16][64];
    __shared__ float Xs[16][64];
    const int b = blockIdx.z;
    const float* Ab = A + aBS * b;
    const float* Xb = X + xBS * b;
    float* Ob = O + oBS * b;
    const int m0 = blockIdx.y * 64;
    const int n0 = blockIdx.x * 64;
    const int t  = threadIdx.x;
    const int tx = t & 15;
    const int ty = t >> 4;

    float acc[4][4];
#pragma unroll
    for (int i = 0; i < 4; i++)
#pragma unroll
        for (int j = 0; j < 4; j++) acc[i][j] = 0.f;

    const int am = t >> 2;          // 0..63
    const int ak = (t & 3) << 2;    // 0,4,8,12
    const int xk = t >> 4;          // 0..15
    const int xc = (t & 15) << 2;   // 0..60

    for (int k0 = 0; k0 < K; k0 += 16) {
        // load A tile (transposed into As[k][m]); K-contiguous float4 reads
        float4 av = *(const float4*)&Ab[(long)(m0 + am) * K + k0 + ak];
        As[ak + 0][am] = av.x;
        As[ak + 1][am] = av.y;
        As[ak + 2][am] = av.z;
        As[ak + 3][am] = av.w;
        // load X tile; N-contiguous float4 reads
        *(float4*)&Xs[xk][xc] = *(const float4*)&Xb[(long)(k0 + xk) * N + n0 + xc];
        __syncthreads();
#pragma unroll
        for (int kk = 0; kk < 16; kk++) {
            float4 a = *(const float4*)&As[kk][ty * 4];
            float4 x = *(const float4*)&Xs[kk][tx * 4];
            float ar[4] = {a.x, a.y, a.z, a.w};
            float xr[4] = {x.x, x.y, x.z, x.w};
#pragma unroll
            for (int i = 0; i < 4; i++)
#pragma unroll
                for (int j = 0; j < 4; j++) acc[i][j] += ar[i] * xr[j];
        }
        __syncthreads();
    }
#pragma unroll
    for (int i = 0; i < 4; i++) {
        float4 o = make_float4(acc[i][0], acc[i][1], acc[i][2], acc[i][3]);
        *(float4*)&Ob[(long)(m0 + ty * 4 + i) * N + n0 + tx * 4] = o;
    }
}

// ---------------------------------------------------------------------------
// Depthwise 3x3 conv, dilation 2, zero-pad 2 (cross-correlation, XLA style),
// plus fused sum-of-squares accumulation for q,k channels (ch < 384).
__global__ void dwconv_kernel(const float* __restrict__ in,
                              const float* __restrict__ wdw,
                              float* __restrict__ out,
                              float* __restrict__ sumsq)
{
    const int x  = threadIdx.x;   // 0..127
    const int y  = blockIdx.x;    // 0..127
    const int ch = blockIdx.y;    // 0..575
    const int b  = blockIdx.z;    // 0..7
    const float* ip = in + ((long)b * C3 + ch) * HW;
    const float* wp = wdw + ch * 9;
    float w[9];
#pragma unroll
    for (int i = 0; i < 9; i++) w[i] = __ldg(&wp[i]);

    float acc = 0.f;
#pragma unroll
    for (int i = 0; i < 3; i++) {
        int yy = y + 2 * (i - 1);
        if (yy < 0 || yy >= 128) continue;
#pragma unroll
        for (int j = 0; j < 3; j++) {
            int xx = x + 2 * (j - 1);
            if (xx < 0 || xx >= 128) continue;
            acc += w[i * 3 + j] * ip[yy * 128 + xx];
        }
    }
    out[((long)b * C3 + ch) * HW + y * 128 + x] = acc;

    if (ch < 384) {
        float v = acc * acc;
#pragma unroll
        for (int off = 16; off; off >>= 1) v += __shfl_down_sync(0xffffffffu, v, off);
        __shared__ float ws[4];
        int lane = x & 31, warp = x >> 5;
        if (lane == 0) ws[warp] = v;
        __syncthreads();
        if (x == 0) atomicAdd(&sumsq[b * 384 + ch], ws[0] + ws[1] + ws[2] + ws[3]);
    }
}

// ---------------------------------------------------------------------------
// Raw S = q . k^T (24x24 per (b,head)), split-K over 8 chunks of 2048.
// 2x2 register tile per thread (144 compute threads) => 1 LDS per FMA.
__global__ void qk_kernel(const float* __restrict__ qkv, float* __restrict__ Spart)
{
    const int chunk = blockIdx.x;  // 0..7
    const int bh    = blockIdx.y;  // 0..63
    const int b = bh >> 3, h = bh & 7;
    const float* qp = qkv + ((long)b * C3 + h * 24) * HW;
    const float* kp = qkv + ((long)b * C3 + 192 + h * 24) * HW;
    __shared__ float qs[24 * 129];
    __shared__ float ks[24 * 129];
    const int t = threadIdx.x;  // 256
    float a00 = 0.f, a01 = 0.f, a10 = 0.f, a11 = 0.f;
    const int cc = (t / 12) * 2;
    const int dd = (t % 12) * 2;
    int n0 = chunk * 2048;
    for (int it = 0; it < 16; it++, n0 += 128) {
        for (int idx = t; idx < 3072; idx += 256) {
            int r = idx >> 7, ci = idx & 127;
            qs[r * 129 + ci] = qp[(long)r * HW + n0 + ci];
            ks[r * 129 + ci] = kp[(long)r * HW + n0 + ci];
        }
        __syncthreads();
        if (t < 144) {
#pragma unroll 8
            for (int nn = 0; nn < 128; nn++) {
                float q0 = qs[cc * 129 + nn];
                float q1 = qs[(cc + 1) * 129 + nn];
                float k0 = ks[dd * 129 + nn];
                float k1 = ks[(dd + 1) * 129 + nn];
                a00 += q0 * k0; a01 += q0 * k1;
                a10 += q1 * k0; a11 += q1 * k1;
            }
        }
        __syncthreads();
    }
    if (t < 144) {
        float* sp = Spart + ((long)bh * 8 + chunk) * 576;
        sp[cc * 24 + dd]           = a00;
        sp[cc * 24 + dd + 1]       = a01;
        sp[(cc + 1) * 24 + dd]     = a10;
        sp[(cc + 1) * 24 + dd + 1] = a11;
    }
}

// ---------------------------------------------------------------------------
// Per batch: reduce split-K, scale by 1/((|q|+eps)(|k|+eps))*temperature,
// softmax over d, then fold w_proj with A: W2[o,g=h*24+d] = sum_c' wproj[o,h*24+c']*A[h,c',d]
__global__ void softmax_fold_kernel(const float* __restrict__ Spart,
                                    const float* __restrict__ sumsq,
                                    const float* __restrict__ temp,
                                    const float* __restrict__ wproj,
                                    float* __restrict__ W2)
{
    const int b = blockIdx.x;
    const int t = threadIdx.x;  // 256
    __shared__ float A[8 * 576];
    __shared__ float nq[192], nk[192];
    for (int i = t; i < 192; i += 256) {
        nq[i] = sqrtf(sumsq[b * 384 + i]) + 1e-6f;
        nk[i] = sqrtf(sumsq[b * 384 + 192 + i]) + 1e-6f;
    }
    __syncthreads();
    for (int idx = t; idx < 4608; idx += 256) {
        int h = idx / 576, r = idx % 576;
        int c = r / 24, d = r % 24;
        float s = 0.f;
#pragma unroll
        for (int ck = 0; ck < 8; ck++)
            s += Spart[(((long)b * 8 + h) * 8 + ck) * 576 + r];
        A[idx] = s / (nq[h * 24 + c] * nk[h * 24 + d]) * temp[h];
    }
    __syncthreads();
    if (t < 192) {
        int h = t / 24, c = t % 24;
        float* row = &A[h * 576 + c * 24];
        float m = row[0];
        for (int d = 1; d < 24; d++) m = fmaxf(m, row[d]);
        float s = 0.f;
        for (int d = 0; d < 24; d++) { float e = expf(row[d] - m); row[d] = e; s += e; }
        float inv = 1.f / s;
        for (int d = 0; d < 24; d++) row[d] *= inv;
    }
    __syncthreads();
    for (int idx = t; idx < 36864; idx += 256) {
        int o = idx / 192, g = idx % 192;
        int h = g / 24, d = g % 24;
        float s = 0.f;
#pragma unroll
        for (int c = 0; c < 24; c++)
            s += wproj[o * 192 + h * 24 + c] * A[h * 576 + c * 24 + d];
        W2[((long)b * 192 + o) * 192 + g] = s;
    }
}

// ---------------------------------------------------------------------------
extern "C" void kernel_launch(void* const* d_in, const int* in_sizes, int n_in,
                              void* d_out, int out_size)
{
    const float* x      = (const float*)d_in[0];
    const float* w_qkv  = (const float*)d_in[1];
    const float* w_dw   = (const float*)d_in[2];
    const float* w_proj = (const float*)d_in[3];
    const float* temp   = (const float*)d_in[4];
    float* out = (float*)d_out;

    float *qkv_pre, *qkv_post, *sumsq, *Spart, *W2;
    cudaGetSymbolAddress((void**)&qkv_pre,  g_qkv_pre);
    cudaGetSymbolAddress((void**)&qkv_post, g_qkv_post);
    cudaGetSymbolAddress((void**)&sumsq,    g_sumsq);
    cudaGetSymbolAddress((void**)&Spart,    g_Spart);
    cudaGetSymbolAddress((void**)&W2,       g_W2);

    // zero sum-of-squares accumulators
    zero_kernel<<<(NB * 384 + 255) / 256, 256>>>(sumsq, NB * 384);

    // K1: qkv = w_qkv @ x   (per batch: [576,192] x [192,16384])
    gemm64x64<<<dim3(HW / 64, C3 / 64, NB), 256>>>(
        w_qkv, 0L, x, (long)CC * HW, qkv_pre, (long)C3 * HW, C3, CC, HW);

    // K2: depthwise 3x3 dil-2 conv + fused q/k sumsq
    dwconv_kernel<<<dim3(128, C3, NB), 128>>>(qkv_pre, w_dw, qkv_post, sumsq);

    // K3: raw S = q.k^T with split-K partials
    qk_kernel<<<dim3(8, 64), 256>>>(qkv_post, Spart);

    // K4: normalize + softmax + fold proj into W2
    softmax_fold_kernel<<<NB, 256>>>(Spart, sumsq, temp, w_proj, W2);

    // K5: out = W2 @ v  (per batch: [192,192] x [192,16384]) — proj fused
    gemm64x64<<<dim3(HW / 64, CC / 64, NB), 256>>>(
        W2, (long)CC * CC, qkv_post + (long)384 * HW, (long)C3 * HW,
        out, (long)CC * HW, CC, CC, HW);
}